// round 5
// baseline (speedup 1.0000x reference)
#include <cuda_runtime.h>
#include <math.h>

#define NN 8192
#define DD 64
#define CC 100
#define TT 30
#define NPAIR 465      // TT*(TT+1)/2 inclusive-diagonal pairs

// ---- device-global scratch ----
__device__ float g_lp[CC * NN];        // lp[c][n]

typedef unsigned long long u64;

// ---- packed f32x2 helpers (sm_103a FFMA2) ----
__device__ __forceinline__ float2 upk2(u64 v) {
    float2 f; asm("mov.b64 {%0, %1}, %2;" : "=f"(f.x), "=f"(f.y) : "l"(v)); return f;
}
__device__ __forceinline__ u64 fma2(u64 a, u64 b, u64 c) {
    u64 d; asm("fma.rn.f32x2 %0, %1, %2, %3;" : "=l"(d) : "l"(a), "l"(b), "l"(c)); return d;
}
__device__ __forceinline__ u64 add2(u64 a, u64 b) {
    u64 d; asm("add.rn.f32x2 %0, %1, %2;" : "=l"(d) : "l"(a), "l"(b)); return d;
}

// ---- flow: block = 128 samples x 1 class; thread = 1 chain ----
// grid (N/128, C)
__global__ void __launch_bounds__(128, 4) flow_kernel(const float* __restrict__ x,
                                                      const float* __restrict__ z0g,
                                                      const float* __restrict__ apg,
                                                      const float* __restrict__ bpg) {
    __shared__ __align__(16) float sz0[TT * DD];     // 7680 B
    __shared__ __align__(16) float sG[TT * 32];      // 3840 B
    __shared__ float sal[32], sbe[32], sn0[32];
    __shared__ __align__(16) float sp[TT * 128];     // 15360 B

    const int tid = threadIdx.x;
    const int c = blockIdx.y;
    const int n = blockIdx.x * 128 + tid;

    // ---- stage z0[c] (coalesced float4) ----
    {
        const float4* gz = (const float4*)(z0g + (size_t)c * TT * DD);
        float4* s4 = (float4*)sz0;
        #pragma unroll
        for (int i = tid; i < 480; i += 128) s4[i] = gz[i];
    }
    // ---- softplus params (threads 0..29) ----
    if (tid < TT) {
        float a  = log1pf(__expf(apg[c * TT + tid]));
        float be = log1pf(__expf(bpg[c * TT + tid])) - a;
        sal[tid] = a;
        sbe[tid] = be;
    }
    // ---- own x row -> packed regs (L2-resident) + q0 ----
    u64 xv[32];
    {
        const float4* xp = (const float4*)(x + (size_t)n * DD);
        #pragma unroll
        for (int j = 0; j < 16; ++j) {
            float4 v = __ldg(xp + j);
            asm("mov.b64 %0, {%1, %2};" : "=l"(xv[2 * j])     : "f"(v.x), "f"(v.y));
            asm("mov.b64 %0, {%1, %2};" : "=l"(xv[2 * j + 1]) : "f"(v.z), "f"(v.w));
        }
    }
    float q0;
    {
        u64 a0 = 0ull, a1 = 0ull, a2 = 0ull, a3 = 0ull;
        #pragma unroll
        for (int j = 0; j < 32; j += 4) {
            a0 = fma2(xv[j],     xv[j],     a0);
            a1 = fma2(xv[j + 1], xv[j + 1], a1);
            a2 = fma2(xv[j + 2], xv[j + 2], a2);
            a3 = fma2(xv[j + 3], xv[j + 3], a3);
        }
        float2 f = upk2(add2(add2(a0, a1), add2(a2, a3)));
        q0 = f.x + f.y;
    }
    __syncthreads();

    // ---- inline Gram (incl. diagonal -> n0) ----
    for (int k = tid; k < NPAIR; k += 128) {
        int t = (int)((__fsqrt_rn(8.f * k + 1.f) - 1.f) * 0.5f);
        while ((t + 1) * (t + 2) / 2 <= k) ++t;
        while (t * (t + 1) / 2 > k) --t;
        int i = k - t * (t + 1) / 2;
        const ulonglong2* za = (const ulonglong2*)(sz0 + t * DD);
        const ulonglong2* zb = (const ulonglong2*)(sz0 + i * DD);
        u64 a0 = 0ull, a1 = 0ull, a2 = 0ull, a3 = 0ull;
        #pragma unroll
        for (int j = 0; j < 16; j += 2) {
            ulonglong2 va = za[j],     vb = zb[j];
            ulonglong2 va2 = za[j + 1], vb2 = zb[j + 1];
            a0 = fma2(va.x,  vb.x,  a0);
            a1 = fma2(va.y,  vb.y,  a1);
            a2 = fma2(va2.x, vb2.x, a2);
            a3 = fma2(va2.y, vb2.y, a3);
        }
        float2 f = upk2(add2(add2(a0, a1), add2(a2, a3)));
        float dot = f.x + f.y;
        if (i == t) sn0[t] = dot;
        else        sG[t * 32 + i] = dot;
    }

    // ---- P phase (rolled): p[t] = x . z0[t] ----
    #pragma unroll 1
    for (int t = 0; t < TT; ++t) {
        const ulonglong2* zp = (const ulonglong2*)(sz0 + t * DD);
        u64 a0 = 0ull, a1 = 0ull, a2 = 0ull, a3 = 0ull;
        #pragma unroll
        for (int j = 0; j < 16; j += 2) {
            ulonglong2 v0 = zp[j], v1 = zp[j + 1];
            a0 = fma2(xv[2 * j],     v0.x, a0);
            a1 = fma2(xv[2 * j + 1], v0.y, a1);
            a2 = fma2(xv[2 * j + 2], v1.x, a2);
            a3 = fma2(xv[2 * j + 3], v1.y, a3);
        }
        float2 f = upk2(add2(add2(a0, a1), add2(a2, a3)));
        sp[t * 128 + tid] = f.x + f.y;
    }
    __syncthreads();

    // ---- scalar chain in coefficient space ----
    float w[TT];
    float ld = 0.f, g = 1.f, q = q0;
    #pragma unroll
    for (int t = 0; t < TT; ++t) {
        float acc0 = sp[t * 128 + tid];
        float acc1 = 0.f;
        const float* Gr = sG + t * 32;
        int i = 0;
        #pragma unroll
        for (; i + 4 <= t; i += 4) {
            float4 g4 = *(const float4*)(Gr + i);
            acc0 = fmaf(w[i],     g4.x, acc0);
            acc1 = fmaf(w[i + 1], g4.y, acc1);
            acc0 = fmaf(w[i + 2], g4.z, acc0);
            acc1 = fmaf(w[i + 3], g4.w, acc1);
        }
        #pragma unroll
        for (; i < t; ++i) acc0 = fmaf(w[i], Gr[i], acc0);
        float s = g * (acc0 + acc1);

        float al = sal[t], be = sbe[t], nn = sn0[t];
        float r2 = fmaxf(fmaf(-2.f, s, q) + nn, 1e-20f);
        float rin = rsqrtf(r2);
        float r = r2 * rin;
        float h = __fdividef(1.f, al + r);
        float bh = be * h;
        float opbh = 1.f + bh;
        float t2 = opbh - bh * h * r;
        ld += 63.f * __logf(opbh) + __logf(t2);
        q = fmaf(bh * bh, r2, fmaf(2.f * bh, q - s, q));
        float g2 = g * opbh;
        w[t] = -__fdividef(bh, g2);
        g = g2;
    }

    g_lp[(size_t)c * NN + n] = ld - 0.5f * q - 58.8120661251f;
}

// ---- epilogue: warp = sample ----
__global__ void __launch_bounds__(256) out_kernel(const float* __restrict__ x,
                                                  const int* __restrict__ labels,
                                                  const float* __restrict__ freq,
                                                  const float* __restrict__ W,
                                                  const float* __restrict__ b,
                                                  float* __restrict__ out) {
    __shared__ __align__(16) float sWt[CC * 68];
    __shared__ __align__(16) float sxr[8 * 68];
    __shared__ float sb[CC], slf[CC];
    const int tid = threadIdx.x;
    for (int i = tid; i < DD * CC; i += 256) {
        int d = i / CC, cc = i % CC;
        sWt[cc * 68 + d] = W[i];
    }
    for (int i = tid; i < CC; i += 256) { sb[i] = b[i]; slf[i] = __logf(freq[i]); }

    const int wid = tid >> 5, lane = tid & 31;
    const int n = blockIdx.x * 8 + wid;
    {
        const float2* xp = (const float2*)(x + (size_t)n * DD);
        ((float2*)(sxr + wid * 68))[lane] = xp[lane];
    }
    __syncthreads();

    u64 xv[32];
    {
        const ulonglong2* xr = (const ulonglong2*)(sxr + wid * 68);
        #pragma unroll
        for (int j = 0; j < 16; ++j) {
            ulonglong2 v = xr[j];
            xv[2 * j] = v.x; xv[2 * j + 1] = v.y;
        }
    }

    float lg[4], lq[4];
    float mlg = -1e30f, mlp = -1e30f;
    #pragma unroll
    for (int k = 0; k < 4; ++k) {
        int cc = lane + 32 * k;
        if (cc < CC) {
            const ulonglong2* wr = (const ulonglong2*)(sWt + cc * 68);
            u64 a0 = 0ull, a1 = 0ull;
            #pragma unroll
            for (int j = 0; j < 16; ++j) {
                ulonglong2 v = wr[j];
                a0 = fma2(xv[2 * j],     v.x, a0);
                a1 = fma2(xv[2 * j + 1], v.y, a1);
            }
            float2 f = upk2(add2(a0, a1));
            lg[k] = f.x + f.y + sb[cc];
            lq[k] = g_lp[(size_t)cc * NN + n] + slf[cc];
        } else {
            lg[k] = -1e30f; lq[k] = -1e30f;
        }
        mlg = fmaxf(mlg, lg[k]);
        mlp = fmaxf(mlp, lq[k]);
    }
    #pragma unroll
    for (int o = 16; o; o >>= 1) {
        mlg = fmaxf(mlg, __shfl_xor_sync(0xffffffffu, mlg, o));
        mlp = fmaxf(mlp, __shfl_xor_sync(0xffffffffu, mlp, o));
    }
    float se = 0.f, sl = 0.f;
    #pragma unroll
    for (int k = 0; k < 4; ++k) {
        if (lane + 32 * k < CC) {
            se += __expf(lq[k] - mlp);
            sl += __expf(lg[k] - mlg);
        }
    }
    #pragma unroll
    for (int o = 16; o; o >>= 1) {
        se += __shfl_xor_sync(0xffffffffu, se, o);
        sl += __shfl_xor_sync(0xffffffffu, sl, o);
    }
    float marg = mlp + __logf(se);
    float logev = fminf(marg + 80.992775903f, 10.f);
    float E = __expf(logev) / sl;

    float* o = out + (size_t)n * (CC + 1);
    #pragma unroll
    for (int k = 0; k < 4; ++k) {
        int cc = lane + 32 * k;
        if (cc < CC)
            o[cc] = __logf(fmaf(E, __expf(lg[k] - mlg), 1.f));
    }
    if (lane == 0)
        o[CC] = g_lp[(size_t)labels[n] * NN + n];
}

extern "C" void kernel_launch(void* const* d_in, const int* in_sizes, int n_in,
                              void* d_out, int out_size) {
    const float* x      = (const float*)d_in[0];
    const int*   labels = (const int*)d_in[1];
    const float* freq   = (const float*)d_in[2];
    const float* z0     = (const float*)d_in[3];
    const float* ap     = (const float*)d_in[4];
    const float* bp     = (const float*)d_in[5];
    const float* W      = (const float*)d_in[6];
    const float* b      = (const float*)d_in[7];
    float* out = (float*)d_out;

    dim3 grid(NN / 128, CC);
    flow_kernel<<<grid, 128>>>(x, z0, ap, bp);
    out_kernel<<<NN / 8, 256>>>(x, labels, freq, W, b, out);
}

// round 6
// speedup vs baseline: 2.0317x; 2.0317x over previous
#include <cuda_runtime.h>
#include <math.h>

#define NN 8192
#define DD 64
#define CC 100
#define TT 30
#define NPAIR 465      // TT*(TT+1)/2

// ---- device-global scratch ----
__device__ float g_lp[NN * CC];        // lp[n][c]  (transposed for out_kernel)
__device__ float g_G[CC * TT * 32];    // Gram rows pitch 32
__device__ float g_al[CC * 32];
__device__ float g_be[CC * 32];
__device__ float g_n0[CC * 32];

typedef unsigned long long u64;

__device__ __forceinline__ float2 upk2(u64 v) {
    float2 f; asm("mov.b64 {%0, %1}, %2;" : "=f"(f.x), "=f"(f.y) : "l"(v)); return f;
}
__device__ __forceinline__ u64 fma2(u64 a, u64 b, u64 c) {
    u64 d; asm("fma.rn.f32x2 %0, %1, %2, %3;" : "=l"(d) : "l"(a), "l"(b), "l"(c)); return d;
}
__device__ __forceinline__ u64 add2(u64 a, u64 b) {
    u64 d; asm("add.rn.f32x2 %0, %1, %2;" : "=l"(d) : "l"(a), "l"(b)); return d;
}

// ---- prep: per-class params + Gram, conflict-free pitch-65 staging ----
__global__ void __launch_bounds__(512) prep_kernel(const float* __restrict__ z0,
                                                   const float* __restrict__ ap,
                                                   const float* __restrict__ bp) {
    __shared__ float sz[TT * 65];          // pitch 65: rows hit distinct banks
    const int tid = threadIdx.x;
    const int c = blockIdx.x;

    for (int i = tid; i < TT * DD; i += 512) {
        int r = i >> 6, col = i & 63;
        sz[r * 65 + col] = z0[(size_t)c * TT * DD + i];
    }
    if (tid < TT) {
        float a  = log1pf(__expf(ap[c * TT + tid]));
        float be = log1pf(__expf(bp[c * TT + tid])) - a;
        g_al[c * 32 + tid] = a;
        g_be[c * 32 + tid] = be;
    }
    __syncthreads();

    int k = tid;
    if (k < NPAIR) {
        int t = (int)((__fsqrt_rn(8.f * k + 1.f) - 1.f) * 0.5f);
        while ((t + 1) * (t + 2) / 2 <= k) ++t;
        while (t * (t + 1) / 2 > k) --t;
        int i = k - t * (t + 1) / 2;
        const float* za = sz + t * 65;
        const float* zb = sz + i * 65;
        float a0 = 0.f, a1 = 0.f, a2 = 0.f, a3 = 0.f;
        #pragma unroll
        for (int d = 0; d < DD; d += 4) {
            a0 = fmaf(za[d],     zb[d],     a0);
            a1 = fmaf(za[d + 1], zb[d + 1], a1);
            a2 = fmaf(za[d + 2], zb[d + 2], a2);
            a3 = fmaf(za[d + 3], zb[d + 3], a3);
        }
        float dot = (a0 + a1) + (a2 + a3);
        if (i == t) g_n0[c * 32 + t] = dot;
        else        g_G[(size_t)c * TT * 32 + t * 32 + i] = dot;
    }
}

// ---- flow: block = 128 samples x 1 class; half-tile x staging ----
// grid (N/128, C)
__global__ void __launch_bounds__(128, 4) flow_kernel(const float* __restrict__ x,
                                                      const float* __restrict__ z0g) {
    __shared__ __align__(16) float sz0[TT * DD];     // 7680 B
    __shared__ __align__(16) float sG[TT * 32];      // 3840 B
    __shared__ float sal[32], sbe[32], sn0[32];
    __shared__ __align__(16) float sxt[64 * 68];     // 17408 B (half tile)
    __shared__ __align__(16) float sp[TT * 128];     // 15360 B

    const int tid = threadIdx.x;
    const int c = blockIdx.y;
    const int nbase = blockIdx.x * 128;

    // stage z0 + G + params
    {
        const float4* gz = (const float4*)(z0g + (size_t)c * TT * DD);
        float4* s4 = (float4*)sz0;
        #pragma unroll
        for (int i = tid; i < 480; i += 128) s4[i] = gz[i];
    }
    {
        const float4* gg = (const float4*)(g_G + (size_t)c * TT * 32);
        float4* s4 = (float4*)sG;
        #pragma unroll
        for (int i = tid; i < 240; i += 128) s4[i] = gg[i];
    }
    if (tid < TT) {
        sal[tid] = g_al[c * 32 + tid];
        sbe[tid] = g_be[c * 32 + tid];
        sn0[tid] = g_n0[c * 32 + tid];
    }

    u64 xv[32];
    float q0 = 0.f;
    float4* sx4 = (float4*)sxt;

    // ---- pass A: rows 0..63 ----
    {
        const float4* gx = (const float4*)(x + (size_t)nbase * DD);
        #pragma unroll
        for (int it = 0; it < 8; ++it) {
            int idx = tid + 128 * it;
            int r = idx >> 4, col = idx & 15;
            sx4[r * 17 + col] = gx[idx];
        }
    }
    __syncthreads();
    if (tid < 64) {
        const ulonglong2* xr = (const ulonglong2*)(sxt + tid * 68);
        #pragma unroll
        for (int j = 0; j < 16; ++j) {
            ulonglong2 v = xr[j];
            xv[2 * j] = v.x; xv[2 * j + 1] = v.y;
        }
    }
    __syncthreads();
    // ---- pass B: rows 64..127 ----
    {
        const float4* gx = (const float4*)(x + (size_t)(nbase + 64) * DD);
        #pragma unroll
        for (int it = 0; it < 8; ++it) {
            int idx = tid + 128 * it;
            int r = idx >> 4, col = idx & 15;
            sx4[r * 17 + col] = gx[idx];
        }
    }
    __syncthreads();
    if (tid >= 64) {
        const ulonglong2* xr = (const ulonglong2*)(sxt + (tid - 64) * 68);
        #pragma unroll
        for (int j = 0; j < 16; ++j) {
            ulonglong2 v = xr[j];
            xv[2 * j] = v.x; xv[2 * j + 1] = v.y;
        }
    }
    // q0 = ||x||^2
    {
        u64 a0 = 0ull, a1 = 0ull, a2 = 0ull, a3 = 0ull;
        #pragma unroll
        for (int j = 0; j < 32; j += 4) {
            a0 = fma2(xv[j],     xv[j],     a0);
            a1 = fma2(xv[j + 1], xv[j + 1], a1);
            a2 = fma2(xv[j + 2], xv[j + 2], a2);
            a3 = fma2(xv[j + 3], xv[j + 3], a3);
        }
        float2 f = upk2(add2(add2(a0, a1), add2(a2, a3)));
        q0 = f.x + f.y;
    }

    // ---- P phase: p[t] = x . z0[t]  (z0 broadcast, conflict-free) ----
    #pragma unroll 1
    for (int t = 0; t < TT; ++t) {
        const ulonglong2* zp = (const ulonglong2*)(sz0 + t * DD);
        u64 a0 = 0ull, a1 = 0ull, a2 = 0ull, a3 = 0ull;
        #pragma unroll
        for (int j = 0; j < 16; j += 2) {
            ulonglong2 v0 = zp[j], v1 = zp[j + 1];
            a0 = fma2(xv[2 * j],     v0.x, a0);
            a1 = fma2(xv[2 * j + 1], v0.y, a1);
            a2 = fma2(xv[2 * j + 2], v1.x, a2);
            a3 = fma2(xv[2 * j + 3], v1.y, a3);
        }
        float2 f = upk2(add2(add2(a0, a1), add2(a2, a3)));
        sp[t * 128 + tid] = f.x + f.y;   // own slot; no sync needed
    }

    // ---- scalar chain (log-free accumulation, 3 MUFU/step) ----
    float w[TT];
    float g = 1.f, gi = 1.f, q = q0, prod = 1.f;
    #pragma unroll
    for (int t = 0; t < TT; ++t) {
        float acc0 = sp[t * 128 + tid];
        float acc1 = 0.f;
        const float* Gr = sG + t * 32;
        int i = 0;
        #pragma unroll
        for (; i + 4 <= t; i += 4) {
            float4 g4 = *(const float4*)(Gr + i);
            acc0 = fmaf(w[i],     g4.x, acc0);
            acc1 = fmaf(w[i + 1], g4.y, acc1);
            acc0 = fmaf(w[i + 2], g4.z, acc0);
            acc1 = fmaf(w[i + 3], g4.w, acc1);
        }
        #pragma unroll
        for (; i < t; ++i) acc0 = fmaf(w[i], Gr[i], acc0);
        float s = g * (acc0 + acc1);

        float al = sal[t], be = sbe[t], nn = sn0[t];
        float r2 = fmaxf(fmaf(-2.f, s, q) + nn, 1e-20f);
        float rin = rsqrtf(r2);                 // MUFU 1
        float r = r2 * rin;
        float den = al + r;
        float h = __frcp_rn(den);               // MUFU 2  (h = 1/(al+r))
        float v = __frcp_rn(den + be);          // MUFU 3  (v = 1/(al+r+be))
        float bh = be * h;
        float opbh = 1.f + bh;
        float t2 = opbh - bh * (h * r);
        prod *= t2;
        q = fmaf(bh * bh, r2, fmaf(2.f * bh, q - s, q));
        g *= opbh;
        gi *= den * v;                          // gi = 1/g
        w[t] = -bh * gi;
    }

    float lp = 63.f * __logf(g) + __logf(prod) - 0.5f * q - 58.8120661251f;
    g_lp[(size_t)(nbase + tid) * CC + c] = lp;
}

// ---- epilogue: warp = sample ----
__global__ void __launch_bounds__(256) out_kernel(const float* __restrict__ x,
                                                  const int* __restrict__ labels,
                                                  const float* __restrict__ freq,
                                                  const float* __restrict__ W,
                                                  const float* __restrict__ b,
                                                  float* __restrict__ out) {
    __shared__ __align__(16) float sWt[CC * 68];
    __shared__ __align__(16) float sxr[8 * 68];
    __shared__ float sb[CC], slf[CC];
    const int tid = threadIdx.x;
    for (int i = tid; i < DD * CC; i += 256) {
        int d = i / CC, cc = i % CC;
        sWt[cc * 68 + d] = W[i];
    }
    for (int i = tid; i < CC; i += 256) { sb[i] = b[i]; slf[i] = __logf(freq[i]); }

    const int wid = tid >> 5, lane = tid & 31;
    const int n = blockIdx.x * 8 + wid;
    {
        const float2* xp = (const float2*)(x + (size_t)n * DD);
        ((float2*)(sxr + wid * 68))[lane] = xp[lane];
    }
    __syncthreads();

    u64 xv[32];
    {
        const ulonglong2* xr = (const ulonglong2*)(sxr + wid * 68);
        #pragma unroll
        for (int j = 0; j < 16; ++j) {
            ulonglong2 v = xr[j];
            xv[2 * j] = v.x; xv[2 * j + 1] = v.y;
        }
    }

    const float* lprow = g_lp + (size_t)n * CC;
    float lg[4], lq[4];
    float mlg = -1e30f, mlp = -1e30f;
    #pragma unroll
    for (int k = 0; k < 4; ++k) {
        int cc = lane + 32 * k;
        if (cc < CC) {
            const ulonglong2* wr = (const ulonglong2*)(sWt + cc * 68);
            u64 a0 = 0ull, a1 = 0ull;
            #pragma unroll
            for (int j = 0; j < 16; ++j) {
                ulonglong2 v = wr[j];
                a0 = fma2(xv[2 * j],     v.x, a0);
                a1 = fma2(xv[2 * j + 1], v.y, a1);
            }
            float2 f = upk2(add2(a0, a1));
            lg[k] = f.x + f.y + sb[cc];
            lq[k] = lprow[cc] + slf[cc];
        } else {
            lg[k] = -1e30f; lq[k] = -1e30f;
        }
        mlg = fmaxf(mlg, lg[k]);
        mlp = fmaxf(mlp, lq[k]);
    }
    #pragma unroll
    for (int o = 16; o; o >>= 1) {
        mlg = fmaxf(mlg, __shfl_xor_sync(0xffffffffu, mlg, o));
        mlp = fmaxf(mlp, __shfl_xor_sync(0xffffffffu, mlp, o));
    }
    float se = 0.f, sl = 0.f;
    #pragma unroll
    for (int k = 0; k < 4; ++k) {
        if (lane + 32 * k < CC) {
            se += __expf(lq[k] - mlp);
            sl += __expf(lg[k] - mlg);
        }
    }
    #pragma unroll
    for (int o = 16; o; o >>= 1) {
        se += __shfl_xor_sync(0xffffffffu, se, o);
        sl += __shfl_xor_sync(0xffffffffu, sl, o);
    }
    float marg = mlp + __logf(se);
    float logev = fminf(marg + 80.992775903f, 10.f);
    float E = __expf(logev) / sl;

    float* o = out + (size_t)n * (CC + 1);
    #pragma unroll
    for (int k = 0; k < 4; ++k) {
        int cc = lane + 32 * k;
        if (cc < CC)
            o[cc] = __logf(fmaf(E, __expf(lg[k] - mlg), 1.f));
    }
    if (lane == 0)
        o[CC] = lprow[labels[n]];
}

extern "C" void kernel_launch(void* const* d_in, const int* in_sizes, int n_in,
                              void* d_out, int out_size) {
    const float* x      = (const float*)d_in[0];
    const int*   labels = (const int*)d_in[1];
    const float* freq   = (const float*)d_in[2];
    const float* z0     = (const float*)d_in[3];
    const float* ap     = (const float*)d_in[4];
    const float* bp     = (const float*)d_in[5];
    const float* W      = (const float*)d_in[6];
    const float* b      = (const float*)d_in[7];
    float* out = (float*)d_out;

    prep_kernel<<<CC, 512>>>(z0, ap, bp);
    dim3 grid(NN / 128, CC);
    flow_kernel<<<grid, 128>>>(x, z0);
    out_kernel<<<NN / 8, 256>>>(x, labels, freq, W, b, out);
}